// round 1
// baseline (speedup 1.0000x reference)
#include <cuda_runtime.h>

#define NB 256

// ---------------- device scratch (no allocs allowed) ----------------
__device__ unsigned char g_m1[NB * 64 * 64];
__device__ unsigned char g_m2[NB * 32 * 32];
__device__ unsigned char g_m3[NB * 32 * 32];
__device__ unsigned char g_m4[NB * 16 * 16];
__device__ float g_p1[NB * 32 * 32 * 32];   // [b][32ch][32][32]
__device__ float g_p2[NB * 64 * 16 * 16];   // [b][64ch][16][16]  (== flat [b][16384])
__device__ float g_fc1p[32 * NB * 128];     // split-K partials

// ---------------- masks ----------------
// m1[i][j] = (sum c[i..i+2][j..j+2], clamped at 63) >= 2
// m2 = 2x2 pool-sum of m1 >= 2 ; m3 = win3 of m2 >= 2 ; m4 = 2x2 pool of m3 >= 2
__global__ void masks_kernel(const int* __restrict__ c_map) {
    int b = blockIdx.x, t = threadIdx.x;
    __shared__ unsigned char cs[64 * 64];
    __shared__ unsigned char m1s[64 * 64];
    __shared__ unsigned char m2s[32 * 32];
    __shared__ unsigned char m3s[32 * 32];

    for (int i = t; i < 4096; i += 256) cs[i] = (unsigned char)c_map[b * 4096 + i];
    __syncthreads();
    for (int i = t; i < 4096; i += 256) {
        int r = i >> 6, c = i & 63, s = 0;
        #pragma unroll
        for (int dr = 0; dr < 3; ++dr) {
            int rr = r + dr;
            if (rr < 64)
                #pragma unroll
                for (int dc = 0; dc < 3; ++dc) {
                    int cc = c + dc;
                    if (cc < 64) s += cs[rr * 64 + cc];
                }
        }
        m1s[i] = (s > 1);
    }
    __syncthreads();
    for (int i = t; i < 4096; i += 256) g_m1[b * 4096 + i] = m1s[i];
    for (int i = t; i < 1024; i += 256) {
        int r = i >> 5, c = i & 31;
        int s = m1s[(2*r)*64 + 2*c] + m1s[(2*r)*64 + 2*c + 1]
              + m1s[(2*r+1)*64 + 2*c] + m1s[(2*r+1)*64 + 2*c + 1];
        m2s[i] = (s > 1);
    }
    __syncthreads();
    for (int i = t; i < 1024; i += 256) g_m2[b * 1024 + i] = m2s[i];
    for (int i = t; i < 1024; i += 256) {
        int r = i >> 5, c = i & 31, s = 0;
        #pragma unroll
        for (int dr = 0; dr < 3; ++dr) {
            int rr = r + dr;
            if (rr < 32)
                #pragma unroll
                for (int dc = 0; dc < 3; ++dc) {
                    int cc = c + dc;
                    if (cc < 32) s += m2s[rr * 32 + cc];
                }
        }
        m3s[i] = (s > 1);
    }
    __syncthreads();
    for (int i = t; i < 1024; i += 256) g_m3[b * 1024 + i] = m3s[i];
    for (int i = t; i < 256; i += 256) {
        int r = i >> 4, c = i & 15;
        int s = m3s[(2*r)*32 + 2*c] + m3s[(2*r)*32 + 2*c + 1]
              + m3s[(2*r+1)*32 + 2*c] + m3s[(2*r+1)*32 + 2*c + 1];
        g_m4[b * 256 + i] = (s > 1);
    }
}

// ---------------- conv1 (1->32) + m1 gate + relu + maxpool2 + m2 gate ----------------
__global__ __launch_bounds__(256) void conv1_kernel(const float* __restrict__ x,
                                                    const float* __restrict__ W1,
                                                    const float* __restrict__ b1) {
    __shared__ __align__(16) float xt[66 * 68];   // padded input, row stride 68
    __shared__ float w1s[32 * 9];
    __shared__ float b1s[32];
    __shared__ unsigned char m1s[64 * 64];
    __shared__ unsigned char m2s[32 * 32];

    int b = blockIdx.x, t = threadIdx.x;
    for (int i = t; i < 66 * 68; i += 256) xt[i] = 0.f;
    __syncthreads();
    for (int i = t; i < 4096; i += 256) {
        int r = i >> 6, c = i & 63;
        xt[(r + 1) * 68 + (c + 1)] = x[b * 4096 + i];
    }
    for (int i = t; i < 288; i += 256) w1s[i] = W1[i];
    if (t < 32) b1s[t] = b1[t];
    for (int i = t; i < 4096; i += 256) m1s[i] = g_m1[b * 4096 + i];
    for (int i = t; i < 1024; i += 256) m2s[i] = g_m2[b * 1024 + i];
    __syncthreads();

    for (int k = 0; k < 4; ++k) {
        int pp = t + 256 * k;
        int pi = pp >> 5, pj = pp & 31;
        // 4x4 patch (conv rows 2pi,2pi+1 need xt rows 2pi..2pi+3; cols same)
        float p[4][4];
        #pragma unroll
        for (int rr = 0; rr < 4; ++rr) {
            const float* tp = &xt[(2 * pi + rr) * 68 + 2 * pj];
            float2 a = *(const float2*)tp;
            float2 c = *(const float2*)(tp + 2);
            p[rr][0] = a.x; p[rr][1] = a.y; p[rr][2] = c.x; p[rr][3] = c.y;
        }
        unsigned char ma = m1s[(2*pi)*64 + 2*pj],     mb = m1s[(2*pi)*64 + 2*pj + 1];
        unsigned char mc = m1s[(2*pi+1)*64 + 2*pj],   md = m1s[(2*pi+1)*64 + 2*pj + 1];
        bool mm2 = m2s[pi * 32 + pj] != 0;

        for (int oc = 0; oc < 32; ++oc) {
            const float* w = &w1s[oc * 9];
            float bb = b1s[oc];
            float s[4];
            #pragma unroll
            for (int dr = 0; dr < 2; ++dr)
                #pragma unroll
                for (int dc = 0; dc < 2; ++dc) {
                    s[dr * 2 + dc] =
                          p[dr][dc]   * w[0] + p[dr][dc+1]   * w[1] + p[dr][dc+2]   * w[2]
                        + p[dr+1][dc] * w[3] + p[dr+1][dc+1] * w[4] + p[dr+1][dc+2] * w[5]
                        + p[dr+2][dc] * w[6] + p[dr+2][dc+1] * w[7] + p[dr+2][dc+2] * w[8]
                        + bb;
                }
            float v = 0.f;
            if (mm2) {
                if (ma) v = fmaxf(v, s[0]);
                if (mb) v = fmaxf(v, s[1]);
                if (mc) v = fmaxf(v, s[2]);
                if (md) v = fmaxf(v, s[3]);
            }
            g_p1[((b * 32 + oc) * 32 + pi) * 32 + pj] = v;
        }
    }
}

// ---------------- conv2 (32->64) + m3 gate + relu + maxpool2 + m4 gate ----------------
// grid (b=256, half=2, ocgrp=2); 512 threads; dynamic smem.
#define C2_WSM_OFF   0                       // 32oc * 32ic * 12 floats (padded 9->12)
#define C2_TILE_OFF  49152                   // 32ic * 18 * 36 floats
#define C2_BIAS_OFF  (49152 + 82944)
#define C2_M3_OFF    (C2_BIAS_OFF + 128)
#define C2_M4_OFF    (C2_M3_OFF + 512)
#define C2_SMEM      (C2_M4_OFF + 128)

__global__ __launch_bounds__(512, 1) void conv2_kernel(const float* __restrict__ W2,
                                                       const float* __restrict__ b2) {
    extern __shared__ __align__(16) char smraw[];
    float* wsm  = (float*)(smraw + C2_WSM_OFF);
    float* tile = (float*)(smraw + C2_TILE_OFF);
    float* bias = (float*)(smraw + C2_BIAS_OFF);
    unsigned char* m3s = (unsigned char*)(smraw + C2_M3_OFF);
    unsigned char* m4s = (unsigned char*)(smraw + C2_M4_OFF);

    int b = blockIdx.x, h = blockIdx.y, g = blockIdx.z;
    int t = threadIdx.x;

    for (int e = t; e < 32 * 32 * 9; e += 512) {
        int k = e % 9, ic = (e / 9) & 31, o = e / 288;
        wsm[o * 384 + ic * 12 + k] = W2[((g * 32 + o) * 32 + ic) * 9 + k];
    }
    if (t < 32) bias[t] = b2[g * 32 + t];
    if (t < 512) m3s[t] = g_m3[b * 1024 + (h * 16 + (t >> 5)) * 32 + (t & 31)];
    if (t < 128) m4s[t] = g_m4[b * 256 + (h * 8 + (t >> 4)) * 16 + (t & 15)];
    for (int e = t; e < 32 * 18 * 36; e += 512) tile[e] = 0.f;
    __syncthreads();

    int r0 = h * 16 - 1;
    int rv0 = (r0 < 0) ? 0 : r0;         // 17 valid rows either half
    for (int e = t; e < 32 * 17 * 8; e += 512) {
        int q = e & 7, ri = (e >> 3) % 17, ic = e / 136;
        int gr = rv0 + ri, lr = gr - r0;
        float4 v = *(const float4*)&g_p1[((b * 32 + ic) * 32 + gr) * 32 + 4 * q];
        float* dst = &tile[ic * 648 + lr * 36 + 1 + 4 * q];
        dst[0] = v.x; dst[1] = v.y; dst[2] = v.z; dst[3] = v.w;
    }
    __syncthreads();

    int pp = t & 127, og = t >> 7;              // warp-uniform og -> broadcast weight LDS
    int prow = pp >> 4, pcol = pp & 15;
    int lrb = 2 * prow, lcb = 2 * pcol;
    int oc0 = og * 8;

    float acc[8][4];
    #pragma unroll
    for (int o = 0; o < 8; ++o)
        acc[o][0] = acc[o][1] = acc[o][2] = acc[o][3] = 0.f;

    for (int ic = 0; ic < 32; ++ic) {
        const float* tp = &tile[ic * 648 + lrb * 36 + lcb];
        float p[4][4];
        #pragma unroll
        for (int rr = 0; rr < 4; ++rr) {
            float2 a = *(const float2*)(tp + rr * 36);
            float2 c = *(const float2*)(tp + rr * 36 + 2);
            p[rr][0] = a.x; p[rr][1] = a.y; p[rr][2] = c.x; p[rr][3] = c.y;
        }
        const float* wbase = &wsm[oc0 * 384 + ic * 12];
        #pragma unroll
        for (int o = 0; o < 8; ++o) {
            const float* w = wbase + o * 384;
            float4 wa = *(const float4*)w;
            float4 wb = *(const float4*)(w + 4);
            float w8 = w[8];
            #pragma unroll
            for (int dr = 0; dr < 2; ++dr)
                #pragma unroll
                for (int dc = 0; dc < 2; ++dc) {
                    acc[o][dr * 2 + dc] +=
                          p[dr][dc]     * wa.x + p[dr][dc+1]   * wa.y + p[dr][dc+2]   * wa.z
                        + p[dr+1][dc]   * wa.w + p[dr+1][dc+1] * wb.x + p[dr+1][dc+2] * wb.y
                        + p[dr+2][dc]   * wb.z + p[dr+2][dc+1] * wb.w + p[dr+2][dc+2] * w8;
                }
        }
    }

    bool mm4 = m4s[prow * 16 + pcol] != 0;
    unsigned char m3a = m3s[lrb * 32 + lcb],       m3b = m3s[lrb * 32 + lcb + 1];
    unsigned char m3c = m3s[(lrb + 1) * 32 + lcb], m3d = m3s[(lrb + 1) * 32 + lcb + 1];
    int gpr = h * 8 + prow;
    #pragma unroll
    for (int o = 0; o < 8; ++o) {
        float v = 0.f;                       // init 0 == relu fused into fmax chain
        if (mm4) {
            float bb = bias[oc0 + o];
            if (m3a) v = fmaxf(v, acc[o][0] + bb);
            if (m3b) v = fmaxf(v, acc[o][1] + bb);
            if (m3c) v = fmaxf(v, acc[o][2] + bb);
            if (m3d) v = fmaxf(v, acc[o][3] + bb);
        }
        int oc = g * 32 + oc0 + o;
        g_p2[((b * 64 + oc) * 16 + gpr) * 16 + pcol] = v;
    }
}

// ---------------- fc1 split-K GEMM: partial[ks][b][n] ----------------
// grid (8 btiles of 32, 32 ksplits of 512), 256 threads
__global__ __launch_bounds__(256) void fc1_kernel(const float* __restrict__ Wfc1) {
    __shared__ __align__(16) float Asm[32 * 36];     // [bi][j] pad 36
    __shared__ __align__(16) float Bsm[128 * 32];    // [n][j]
    int b0 = blockIdx.x * 32;
    int ks = blockIdx.y;
    int k0 = ks * 512;
    int t = threadIdx.x, lane = t & 31, wid = t >> 5;
    int bi = lane, ng = wid * 16;

    float acc[16];
    #pragma unroll
    for (int q = 0; q < 16; ++q) acc[q] = 0.f;

    for (int kk = 0; kk < 512; kk += 32) {
        for (int r = wid; r < 32; r += 8)
            Asm[r * 36 + lane] = g_p2[(b0 + r) * 16384 + k0 + kk + lane];
        #pragma unroll
        for (int r = 0; r < 16; ++r)
            Bsm[(ng + r) * 32 + lane] = Wfc1[(ng + r) * 16384 + k0 + kk + lane];
        __syncthreads();
        #pragma unroll
        for (int j4 = 0; j4 < 8; ++j4) {
            float4 av = *(const float4*)&Asm[bi * 36 + j4 * 4];
            #pragma unroll
            for (int q = 0; q < 16; ++q) {
                float4 bv = *(const float4*)&Bsm[(ng + q) * 32 + j4 * 4];  // broadcast
                acc[q] += av.x * bv.x + av.y * bv.y + av.z * bv.z + av.w * bv.w;
            }
        }
        __syncthreads();
    }
    #pragma unroll
    for (int q = 0; q < 16; ++q)
        g_fc1p[(ks * NB + b0 + bi) * 128 + ng + q] = acc[q];
}

// ---------------- reduce + bias + relu + fc2 ----------------
__global__ __launch_bounds__(128) void fc2_kernel(const float* __restrict__ Wfc2,
                                                  const float* __restrict__ bfc2,
                                                  const float* __restrict__ bfc1,
                                                  float* __restrict__ out) {
    int b = blockIdx.x, t = threadIdx.x;
    __shared__ float hs[128];
    float s = 0.f;
    #pragma unroll
    for (int ks = 0; ks < 32; ++ks) s += g_fc1p[(ks * NB + b) * 128 + t];
    s += bfc1[t];
    hs[t] = fmaxf(s, 0.f);
    __syncthreads();
    int wid = t >> 5, lane = t & 31;
    for (int o = wid; o < 10; o += 4) {
        float p = 0.f;
        #pragma unroll
        for (int q = 0; q < 4; ++q)
            p += hs[lane + q * 32] * Wfc2[o * 128 + lane + q * 32];
        #pragma unroll
        for (int off = 16; off; off >>= 1)
            p += __shfl_xor_sync(0xffffffffu, p, off);
        if (lane == 0) out[b * 10 + o] = p + bfc2[o];
    }
}

// ---------------- launch ----------------
extern "C" void kernel_launch(void* const* d_in, const int* in_sizes, int n_in,
                              void* d_out, int out_size) {
    (void)in_sizes; (void)n_in; (void)out_size;
    const float* x     = (const float*)d_in[0];
    const int*   c_map = (const int*)d_in[1];
    const float* W1    = (const float*)d_in[2];
    const float* b1    = (const float*)d_in[3];
    const float* W2    = (const float*)d_in[4];
    const float* b2    = (const float*)d_in[5];
    const float* Wfc1  = (const float*)d_in[6];
    const float* bfc1  = (const float*)d_in[7];
    const float* Wfc2  = (const float*)d_in[8];
    const float* bfc2  = (const float*)d_in[9];
    float* out = (float*)d_out;

    masks_kernel<<<NB, 256>>>(c_map);
    conv1_kernel<<<NB, 256>>>(x, W1, b1);
    cudaFuncSetAttribute(conv2_kernel, cudaFuncAttributeMaxDynamicSharedMemorySize, C2_SMEM);
    conv2_kernel<<<dim3(NB, 2, 2), 512, C2_SMEM>>>(W2, b2);
    fc1_kernel<<<dim3(8, 32), 256>>>(Wfc1);
    fc2_kernel<<<NB, 128>>>(Wfc2, bfc2, bfc1, out);
}